// round 5
// baseline (speedup 1.0000x reference)
#include <cuda_runtime.h>
#include <cuda_bf16.h>
#include <cstdint>

#define N_NODES 100000
#define N_EDGES 1600000
#define IN_DIM  128
#define OUT_DIM 64
#define NB_SCAN ((N_NODES + 1023) / 1024)          // 98 scan blocks
#define LIN_BLOCKS ((N_NODES + 255) / 256)         // 391 linear blocks
#define PERM_BLOCKS ((N_EDGES / 4 + 255) / 256)    // 1563 perm blocks (4 edges/thread)
#define ROWS_PER_WARP 4

// Scratch (allocation-free rule: __device__ globals)
__device__ float              g_xw[(size_t)N_NODES * OUT_DIM];    // 25.6 MB
__device__ unsigned long long g_perm[N_EDGES];                    // 12.8 MB {val,col}
__device__ int                g_off[N_NODES];                     // counts -> excl scan -> cursors
__device__ int                g_bsum[NB_SCAN];                    // block totals -> excl prefix

// ---------------------------------------------------------------------------
// hist: counts of edge_row, 4 edges/thread (int4 load, 4 independent atomics)
// ---------------------------------------------------------------------------
__global__ __launch_bounds__(256) void hist_kernel(const int* __restrict__ erow) {
    int i = blockIdx.x * 256 + threadIdx.x;
    if (i * 4 >= N_EDGES) return;
    int4 r = ((const int4*)erow)[i];
    atomicAdd(&g_off[r.x], 1);
    atomicAdd(&g_off[r.y], 1);
    atomicAdd(&g_off[r.z], 1);
    atomicAdd(&g_off[r.w], 1);
}

// ---------------------------------------------------------------------------
// scan1: per-block exclusive scan of counts via warp shuffles (2 syncs)
// ---------------------------------------------------------------------------
__global__ __launch_bounds__(1024) void scan1_kernel() {
    __shared__ int wsum[32];
    int t = threadIdx.x;
    int lane = t & 31, wid = t >> 5;
    int idx = blockIdx.x * 1024 + t;
    int v = (idx < N_NODES) ? g_off[idx] : 0;

    int inc = v;
    #pragma unroll
    for (int d = 1; d < 32; d <<= 1) {
        int n_ = __shfl_up_sync(0xffffffffu, inc, d);
        if (lane >= d) inc += n_;
    }
    if (lane == 31) wsum[wid] = inc;
    __syncthreads();
    if (wid == 0) {
        int w = wsum[lane];
        #pragma unroll
        for (int d = 1; d < 32; d <<= 1) {
            int n_ = __shfl_up_sync(0xffffffffu, w, d);
            if (lane >= d) w += n_;
        }
        wsum[lane] = w;   // inclusive warp-sum scan
    }
    __syncthreads();
    int base = (wid > 0) ? wsum[wid - 1] : 0;
    if (idx < N_NODES) g_off[idx] = base + inc - v;   // exclusive
    if (t == 1023) g_bsum[blockIdx.x] = wsum[31];     // block total
}

// ---------------------------------------------------------------------------
// scan2: exclusive scan of the 98 block totals (one block)
// ---------------------------------------------------------------------------
__global__ void scan2_kernel() {
    __shared__ int s[128];
    int t = threadIdx.x;
    int v = (t < NB_SCAN) ? g_bsum[t] : 0;
    s[t] = v;
    __syncthreads();
    #pragma unroll
    for (int d = 1; d < 128; d <<= 1) {
        int add = (t >= d) ? s[t - d] : 0;
        __syncthreads();
        s[t] += add;
        __syncthreads();
    }
    if (t < NB_SCAN) g_bsum[t] = s[t] - v;
}

// ---------------------------------------------------------------------------
// Fat kernel: blocks [0, LIN_BLOCKS) compute xw = x@W + b; the remaining
// PERM_BLOCKS permute edges into row-sorted order, 4 edges/thread (MLP=4).
// The two halves are independent; perm (latency-bound) hides under linear
// (FMA-bound).
// ---------------------------------------------------------------------------
__global__ __launch_bounds__(256) void fused_linear_perm_kernel(
    const float* __restrict__ x,
    const float* __restrict__ W,
    const float* __restrict__ b,
    const int*   __restrict__ erow,
    const int*   __restrict__ ecol,
    const float* __restrict__ eval,
    float* __restrict__ xw)
{
    __shared__ float Ws[IN_DIM * OUT_DIM];
    __shared__ float bs[OUT_DIM];
    int tid = threadIdx.x;

    if (blockIdx.x >= LIN_BLOCKS) {
        // ---- perm branch: 4 edges per thread ----
        int i = (blockIdx.x - LIN_BLOCKS) * 256 + tid;
        if (i * 4 >= N_EDGES) return;
        int4   r = ((const int4*)erow)[i];
        int4   c = ((const int4*)ecol)[i];
        float4 v = ((const float4*)eval)[i];

        int p0 = atomicAdd(&g_off[r.x], 1) + g_bsum[r.x >> 10];
        int p1 = atomicAdd(&g_off[r.y], 1) + g_bsum[r.y >> 10];
        int p2 = atomicAdd(&g_off[r.z], 1) + g_bsum[r.z >> 10];
        int p3 = atomicAdd(&g_off[r.w], 1) + g_bsum[r.w >> 10];

        g_perm[p0] = ((unsigned long long)(unsigned)__float_as_int(v.x) << 32) | (unsigned)c.x;
        g_perm[p1] = ((unsigned long long)(unsigned)__float_as_int(v.y) << 32) | (unsigned)c.y;
        g_perm[p2] = ((unsigned long long)(unsigned)__float_as_int(v.z) << 32) | (unsigned)c.z;
        g_perm[p3] = ((unsigned long long)(unsigned)__float_as_int(v.w) << 32) | (unsigned)c.w;
        return;
    }

    // ---- linear branch ----
    const float4* W4  = (const float4*)W;
    float4*       Ws4 = (float4*)Ws;
    #pragma unroll
    for (int i = tid; i < (IN_DIM * OUT_DIM) / 4; i += 256) Ws4[i] = W4[i];
    if (tid < OUT_DIM) bs[tid] = b[tid];
    __syncthreads();

    int n = blockIdx.x * 256 + tid;
    if (n >= N_NODES) return;

    unsigned long long acc[OUT_DIM / 2];
    #pragma unroll
    for (int p = 0; p < OUT_DIM / 2; p++) {
        asm("mov.b64 %0, {%1, %2};" : "=l"(acc[p]) : "f"(bs[2 * p]), "f"(bs[2 * p + 1]));
    }

    const float4* xr = (const float4*)(x + (size_t)n * IN_DIM);
    const ulonglong2* Ws2 = (const ulonglong2*)Ws;

    #pragma unroll 2
    for (int k4 = 0; k4 < IN_DIM / 4; k4++) {
        float4 xv = xr[k4];
        #pragma unroll
        for (int j = 0; j < 4; j++) {
            float xk = (j == 0) ? xv.x : (j == 1) ? xv.y : (j == 2) ? xv.z : xv.w;
            unsigned long long xx;
            asm("mov.b64 %0, {%1, %1};" : "=l"(xx) : "f"(xk));
            int k = k4 * 4 + j;
            const ulonglong2* wr = Ws2 + (size_t)k * (OUT_DIM / 4);
            #pragma unroll
            for (int q = 0; q < OUT_DIM / 4; q++) {
                ulonglong2 wv = wr[q];
                asm("fma.rn.f32x2 %0, %1, %2, %0;" : "+l"(acc[2 * q])     : "l"(xx), "l"(wv.x));
                asm("fma.rn.f32x2 %0, %1, %2, %0;" : "+l"(acc[2 * q + 1]) : "l"(xx), "l"(wv.y));
            }
        }
    }

    ulonglong2* dst = (ulonglong2*)(xw + (size_t)n * OUT_DIM);
    #pragma unroll
    for (int q = 0; q < OUT_DIM / 4; q++) {
        ulonglong2 v; v.x = acc[2 * q]; v.y = acc[2 * q + 1];
        dst[q] = v;
    }
}

// ---------------------------------------------------------------------------
// Gather: 4 rows/warp. Full 32-edge chunks run an UNGUARDED fully-unrolled
// path (16 independent LDG.128 batchable -> high MLP); tail chunk guarded.
// Shfl loop induction is warp-uniform throughout.
// ---------------------------------------------------------------------------
__global__ __launch_bounds__(256) void gather_kernel(
    const float* __restrict__ xw,
    float4* __restrict__ out)
{
    int warp = (blockIdx.x * 256 + threadIdx.x) >> 5;
    int lane = threadIdx.x & 31;
    int half = lane >> 4;
    int l16  = lane & 15;
    int r0   = warp * ROWS_PER_WARP;
    if (r0 >= N_NODES) return;

    #pragma unroll
    for (int rr = 0; rr < ROWS_PER_WARP; rr++) {
        int row = r0 + rr;
        if (row >= N_NODES) break;

        int s = (row == 0) ? 0 : (g_off[row - 1] + g_bsum[(row - 1) >> 10]);
        int e = g_off[row] + g_bsum[row >> 10];

        float4 a0 = make_float4(0.f, 0.f, 0.f, 0.f);
        float4 a1 = make_float4(0.f, 0.f, 0.f, 0.f);

        int base = s;
        // ---- full chunks: no predication, max MLP ----
        for (; base + 32 <= e; base += 32) {
            unsigned long long p = __ldg(&g_perm[base + lane]);
            unsigned plo = (unsigned)p;
            unsigned phi = (unsigned)(p >> 32);
            #pragma unroll
            for (int j = 0; j < 32; j += 4) {
                unsigned c0 = __shfl_sync(0xffffffffu, plo, j + half);
                unsigned v0 = __shfl_sync(0xffffffffu, phi, j + half);
                unsigned c1 = __shfl_sync(0xffffffffu, plo, j + 2 + half);
                unsigned v1 = __shfl_sync(0xffffffffu, phi, j + 2 + half);
                float4 x0 = __ldg(((const float4*)(xw + (size_t)c0 * OUT_DIM)) + l16);
                float4 x1 = __ldg(((const float4*)(xw + (size_t)c1 * OUT_DIM)) + l16);
                float f0 = __int_as_float((int)v0);
                float f1 = __int_as_float((int)v1);
                a0.x = fmaf(x0.x, f0, a0.x); a0.y = fmaf(x0.y, f0, a0.y);
                a0.z = fmaf(x0.z, f0, a0.z); a0.w = fmaf(x0.w, f0, a0.w);
                a1.x = fmaf(x1.x, f1, a1.x); a1.y = fmaf(x1.y, f1, a1.y);
                a1.z = fmaf(x1.z, f1, a1.z); a1.w = fmaf(x1.w, f1, a1.w);
            }
        }
        // ---- tail chunk (m < 32), guarded ----
        int m = e - base;
        if (m > 0) {
            unsigned long long p = 0;
            if (lane < m) p = __ldg(&g_perm[base + lane]);
            unsigned plo = (unsigned)p;
            unsigned phi = (unsigned)(p >> 32);
            for (int j = 0; j < m; j += 4) {           // j warp-uniform
                int i0 = j + half;
                int i1 = j + 2 + half;
                unsigned c0 = __shfl_sync(0xffffffffu, plo, i0);
                unsigned v0 = __shfl_sync(0xffffffffu, phi, i0);
                unsigned c1 = __shfl_sync(0xffffffffu, plo, i1);
                unsigned v1 = __shfl_sync(0xffffffffu, phi, i1);
                if (i0 < m) {
                    float4 x0 = __ldg(((const float4*)(xw + (size_t)c0 * OUT_DIM)) + l16);
                    float f0 = __int_as_float((int)v0);
                    a0.x = fmaf(x0.x, f0, a0.x); a0.y = fmaf(x0.y, f0, a0.y);
                    a0.z = fmaf(x0.z, f0, a0.z); a0.w = fmaf(x0.w, f0, a0.w);
                }
                if (i1 < m) {
                    float4 x1 = __ldg(((const float4*)(xw + (size_t)c1 * OUT_DIM)) + l16);
                    float f1 = __int_as_float((int)v1);
                    a1.x = fmaf(x1.x, f1, a1.x); a1.y = fmaf(x1.y, f1, a1.y);
                    a1.z = fmaf(x1.z, f1, a1.z); a1.w = fmaf(x1.w, f1, a1.w);
                }
            }
        }

        float4 acc;
        acc.x = a0.x + a1.x; acc.y = a0.y + a1.y;
        acc.z = a0.z + a1.z; acc.w = a0.w + a1.w;
        acc.x += __shfl_xor_sync(0xffffffffu, acc.x, 16);
        acc.y += __shfl_xor_sync(0xffffffffu, acc.y, 16);
        acc.z += __shfl_xor_sync(0xffffffffu, acc.z, 16);
        acc.w += __shfl_xor_sync(0xffffffffu, acc.w, 16);

        if (half == 0) {
            acc.x = fmaxf(acc.x, 0.f);
            acc.y = fmaxf(acc.y, 0.f);
            acc.z = fmaxf(acc.z, 0.f);
            acc.w = fmaxf(acc.w, 0.f);
            out[(size_t)row * (OUT_DIM / 4) + l16] = acc;
        }
    }
}

// ---------------------------------------------------------------------------
extern "C" void kernel_launch(void* const* d_in, const int* in_sizes, int n_in,
                              void* d_out, int out_size)
{
    const float* x    = (const float*)d_in[0];
    const int*   erow = (const int*)  d_in[1];
    const int*   ecol = (const int*)  d_in[2];
    const float* eval = (const float*)d_in[3];
    const float* W    = (const float*)d_in[4];
    const float* b    = (const float*)d_in[5];
    float*       out  = (float*)d_out;

    float* xw;  cudaGetSymbolAddress((void**)&xw, g_xw);
    int*   off; cudaGetSymbolAddress((void**)&off, g_off);

    // zero per-row counters (memset node)
    cudaMemsetAsync(off, 0, N_NODES * sizeof(int));

    // histogram of edge_row (4 edges/thread)
    hist_kernel<<<PERM_BLOCKS, 256>>>(erow);

    // two-level exclusive scan of counts
    scan1_kernel<<<NB_SCAN, 1024>>>();
    scan2_kernel<<<1, 128>>>();

    // linear (blocks 0..390) overlapped with edge permutation (rest)
    fused_linear_perm_kernel<<<LIN_BLOCKS + PERM_BLOCKS, 256>>>(
        x, W, b, erow, ecol, eval, xw);

    // out = relu(segment_sum), 4 rows per warp
    {
        int warps  = (N_NODES + ROWS_PER_WARP - 1) / ROWS_PER_WARP;
        int blocks = (warps * 32 + 255) / 256;
        gather_kernel<<<blocks, 256>>>(xw, (float4*)out);
    }
}